// round 13
// baseline (speedup 1.0000x reference)
#include <cuda_runtime.h>
#include <cuda_fp16.h>
#include <cstdint>
#include <cstddef>

// ---------------------------------------------------------------------------
// Problem constants
// ---------------------------------------------------------------------------
#define TT   2048
#define BB   2
#define DD   1024
#define HH   16
#define HDIM 64
#define FFD  4096
#define MM   (TT * BB)          // 4096 rows
#define D3   (3 * DD)           // 3072

// ---------------------------------------------------------------------------
// Scratch (device globals; no runtime allocation allowed)
// ---------------------------------------------------------------------------
__device__ float  g_h   [MM * DD];     // post-LN1 fp32 (residual for LN2)
__device__ float  g_tmp [MM * DD];     // fp32 gemm staging
__device__ __half g_qkv16 [MM * D3];   // fp16 qkv (attention input)
__device__ __half g_x16   [MM * DD];
__device__ __half g_attn16[MM * DD];
__device__ __half g_h16   [MM * DD];
__device__ __half g_ff16  [MM * FFD];
__device__ __half g_wqkv16[D3 * DD];
__device__ __half g_wout16[DD * DD];
__device__ __half g_wfc116[FFD * DD];
__device__ __half g_wfc216[DD * FFD];

__device__ __forceinline__ float gelu_f(float v) {
    const float c = 0.7978845608028654f;   // sqrt(2/pi)
    float t = tanhf(c * (v + 0.044715f * v * v * v));
    return 0.5f * v * (1.0f + t);
}

#define MMA_F16(d0,d1,d2,d3,a0,a1,a2,a3,b0,b1)                                \
    asm volatile(                                                             \
        "mma.sync.aligned.m16n8k16.row.col.f32.f16.f16.f32 "                  \
        "{%0,%1,%2,%3}, {%4,%5,%6,%7}, {%8,%9}, {%0,%1,%2,%3};\n"             \
        : "+f"(d0), "+f"(d1), "+f"(d2), "+f"(d3)                              \
        : "r"(a0), "r"(a1), "r"(a2), "r"(a3), "r"(b0), "r"(b1))

#define LDSM4(r0,r1,r2,r3,addr)                                               \
    asm volatile("ldmatrix.sync.aligned.m8n8.x4.shared.b16 {%0,%1,%2,%3}, [%4];" \
        : "=r"(r0), "=r"(r1), "=r"(r2), "=r"(r3) : "r"(addr))

#define LDSM4T(r0,r1,r2,r3,addr)                                              \
    asm volatile("ldmatrix.sync.aligned.m8n8.x4.trans.shared.b16 {%0,%1,%2,%3}, [%4];" \
        : "=r"(r0), "=r"(r1), "=r"(r2), "=r"(r3) : "r"(addr))

__device__ __forceinline__ void cp16(uint32_t dst, const void* src) {
    asm volatile("cp.async.cg.shared.global [%0], [%1], 16;\n"
                 :: "r"(dst), "l"(src));
}
#define CP_COMMIT() asm volatile("cp.async.commit_group;\n")
#define CP_WAIT(n)  asm volatile("cp.async.wait_group %0;\n" :: "n"(n))

// ---------------------------------------------------------------------------
// Fused fp32 -> fp16 convert over 5 segments (one launch).
// ---------------------------------------------------------------------------
#define CVT_N0 (MM * DD)     // x
#define CVT_N1 (D3 * DD)     // wqkv
#define CVT_N2 (DD * DD)     // wout
#define CVT_N3 (FFD * DD)    // wfc1
#define CVT_N4 (DD * FFD)    // wfc2
#define CVT_TOTAL (CVT_N0 + CVT_N1 + CVT_N2 + CVT_N3 + CVT_N4)

__global__ void __launch_bounds__(256)
f2h5_kernel(const float* __restrict__ s0, __half* __restrict__ d0,
            const float* __restrict__ s1, __half* __restrict__ d1,
            const float* __restrict__ s2, __half* __restrict__ d2,
            const float* __restrict__ s3, __half* __restrict__ d3,
            const float* __restrict__ s4, __half* __restrict__ d4)
{
    long long i = ((long long)blockIdx.x * 256 + threadIdx.x) * 4;
    const float* src;
    __half* dst;
    long long off;
    if (i < CVT_N0)                          { src = s0; dst = d0; off = i; }
    else if (i < CVT_N0 + CVT_N1)            { src = s1; dst = d1; off = i - CVT_N0; }
    else if (i < CVT_N0 + CVT_N1 + CVT_N2)   { src = s2; dst = d2; off = i - CVT_N0 - CVT_N1; }
    else if (i < (long long)CVT_N0 + CVT_N1 + CVT_N2 + CVT_N3)
                                             { src = s3; dst = d3; off = i - CVT_N0 - CVT_N1 - CVT_N2; }
    else if (i < (long long)CVT_TOTAL)       { src = s4; dst = d4; off = i - CVT_N0 - CVT_N1 - CVT_N2 - (long long)CVT_N3; }
    else return;
    float4 v = *(const float4*)(src + off);
    *(__half2*)(dst + off)     = __floats2half2_rn(v.x, v.y);
    *(__half2*)(dst + off + 2) = __floats2half2_rn(v.z, v.w);
}

// ---------------------------------------------------------------------------
// fp16 tensor-core GEMM 128x128: C = A @ W^T + bias (opt. GELU)
// BK=64 (half the barrier rounds of BK=32), 3-stage cp.async, batched
// ldmatrix (12 LDSM then 32 MMAs per 32-half group). 256 thr, 2 CTAs/SM.
// Rows padded to 72 halfs (144B): phases r*16 mod 128 distinct per 8 rows.
// ---------------------------------------------------------------------------
#define BKH      64
#define LDAH     72
#define HSTG     (128 * LDAH)                // halfs per operand per stage
#define HSTAGES  3
#define STGB     (2u * HSTG * 2u)            // stage bytes = 36864
#define GEMMH_SMEM (HSTAGES * (int)STGB)     // 110592 bytes

template <int ACT, int OUTH>
__global__ void __launch_bounds__(256, 2)
gemm_h(const __half* __restrict__ A, const __half* __restrict__ W,
       const float* __restrict__ bias, float* __restrict__ Cf,
       __half* __restrict__ Ch, int M, int N, int K)
{
    extern __shared__ uint32_t sm[];
    const uint32_t smem0 = (uint32_t)__cvta_generic_to_shared(sm);

    const int tid  = threadIdx.x;
    const int m0   = blockIdx.y * 128;
    const int n0   = blockIdx.x * 128;
    const int warp = tid >> 5, lane = tid & 31;
    const int gid  = lane >> 2, tig = lane & 3;
    const int wm   = (warp & 1) * 64;
    const int wn   = (warp >> 1) * 32;

    float acc[4][4][4];
#pragma unroll
    for (int i = 0; i < 4; ++i)
#pragma unroll
        for (int j = 0; j < 4; ++j)
#pragma unroll
            for (int c = 0; c < 4; ++c) acc[i][j][c] = 0.0f;

    // cp.async: thread -> row tid>>1, 32-half slab (tid&1)*32; 4 cp16/operand
    const int lr = tid >> 1;
    const int hc = (tid & 1) << 5;           // 0 or 32 halfs
    const __half* Ag = A + (size_t)(m0 + lr) * K + hc;
    const __half* Wg = W + (size_t)(n0 + lr) * K + hc;
    const uint32_t sA = smem0 + (uint32_t)(lr * LDAH + hc) * 2u;
    const uint32_t sW = sA + (uint32_t)HSTG * 2u;

    auto LOAD = [&](int s, int k0) {
        uint32_t off = (uint32_t)s * STGB;
#pragma unroll
        for (int c = 0; c < 4; ++c) {
            cp16(sA + off + (uint32_t)(c * 16), Ag + k0 + c * 8);
            cp16(sW + off + (uint32_t)(c * 16), Wg + k0 + c * 8);
        }
        CP_COMMIT();
    };

    const uint32_t aBase = smem0 + (uint32_t)((wm + (lane & 15)) * LDAH) * 2u
                                 + (uint32_t)((lane >> 4) << 4);
    const uint32_t bBase = smem0 + (uint32_t)HSTG * 2u
                                 + (uint32_t)((wn + (lane & 7) + ((lane & 16) >> 1)) * LDAH) * 2u
                                 + (uint32_t)(((lane >> 3) & 1) << 4);

    auto COMPUTE = [&](int s) {
        const uint32_t off0 = (uint32_t)s * STGB;
#pragma unroll
        for (int h2 = 0; h2 < 2; ++h2) {         // two 32-half groups
            const uint32_t off = off0 + (uint32_t)(h2 << 6);   // +64 bytes
            uint32_t af[2][4][4], bf[2][4][2];
#pragma unroll
            for (int half = 0; half < 2; ++half) {
                const uint32_t ko = (uint32_t)(half << 5);     // +32 bytes (k16)
#pragma unroll
                for (int mi = 0; mi < 4; ++mi)
                    LDSM4(af[half][mi][0], af[half][mi][1],
                          af[half][mi][2], af[half][mi][3],
                          aBase + off + (uint32_t)(mi * 16 * LDAH * 2) + ko);
#pragma unroll
                for (int p = 0; p < 2; ++p)
                    LDSM4(bf[half][2*p][0],   bf[half][2*p][1],
                          bf[half][2*p+1][0], bf[half][2*p+1][1],
                          bBase + off + (uint32_t)(p * 16 * LDAH * 2) + ko);
            }
#pragma unroll
            for (int half = 0; half < 2; ++half)
#pragma unroll
                for (int mi = 0; mi < 4; ++mi)
#pragma unroll
                    for (int ni = 0; ni < 4; ++ni)
                        MMA_F16(acc[mi][ni][0], acc[mi][ni][1],
                                acc[mi][ni][2], acc[mi][ni][3],
                                af[half][mi][0], af[half][mi][1],
                                af[half][mi][2], af[half][mi][3],
                                bf[half][ni][0], bf[half][ni][1]);
        }
    };

    const int NCH = K / BKH;
    LOAD(0, 0);
    LOAD(1, BKH);
    for (int i = 0; i < NCH; ++i) {
        CP_WAIT(1);                  // chunk i fully landed
        __syncthreads();             // stage (i+2)%3 (chunk i-1) reusable
        if (i + 2 < NCH) LOAD((i + 2) % HSTAGES, (i + 2) * BKH);
        else             CP_COMMIT();
        COMPUTE(i % HSTAGES);
    }
    __syncthreads();

#pragma unroll
    for (int mi = 0; mi < 4; ++mi) {
#pragma unroll
        for (int ni = 0; ni < 4; ++ni) {
            int col = n0 + wn + ni * 8 + 2 * tig;
            float b0 = bias[col], b1 = bias[col + 1];
            int row = m0 + wm + mi * 16 + gid;
            float v0 = acc[mi][ni][0] + b0;
            float v1 = acc[mi][ni][1] + b1;
            float v2 = acc[mi][ni][2] + b0;
            float v3 = acc[mi][ni][3] + b1;
            if (ACT == 1) {
                v0 = gelu_f(v0); v1 = gelu_f(v1);
                v2 = gelu_f(v2); v3 = gelu_f(v3);
            }
            if (OUTH) {
                *(__half2*)(Ch + (size_t)row * N + col)       = __floats2half2_rn(v0, v1);
                *(__half2*)(Ch + (size_t)(row + 8) * N + col) = __floats2half2_rn(v2, v3);
            } else {
                *(float2*)(Cf + (size_t)row * N + col)       = make_float2(v0, v1);
                *(float2*)(Cf + (size_t)(row + 8) * N + col) = make_float2(v2, v3);
            }
        }
    }
}

// ---------------------------------------------------------------------------
// Flash attention (causal), fp16 MMA (R10/R12, passing). qt reversed.
// ---------------------------------------------------------------------------
#define LDQ   72
#define TILEB (64 * LDQ * 2)                   // 9216 bytes
#define ATTN_SMEM (6 * TILEB)                  // 55296 bytes

__global__ void __launch_bounds__(128)
attn_h(const __half* __restrict__ qkv, __half* __restrict__ outp)
{
    extern __shared__ char asmem[];
    const uint32_t smem0 = (uint32_t)__cvta_generic_to_shared(asmem);
    const uint32_t sQ = smem0;
    const uint32_t sP = smem0 + TILEB;
    const uint32_t sK = smem0 + 2 * TILEB;     // 2 stages
    const uint32_t sV = smem0 + 4 * TILEB;     // 2 stages
    __half* Pgen = (__half*)(asmem + TILEB);

    const int qt = (int)gridDim.x - 1 - (int)blockIdx.x;   // longest first
    const int h = blockIdx.y, b = blockIdx.z;
    const int tid = threadIdx.x;
    const int warp = tid >> 5, lane = tid & 31;
    const int gid = lane >> 2, tig = lane & 3;
    const int wr = warp * 16;

    const int qoff = h * HDIM;
    const int koff = DD + h * HDIM;
    const int voff = 2 * DD + h * HDIM;

    for (int i = tid; i < 512; i += 128) {
        int r = i >> 3, c = i & 7;
        cp16(sQ + (uint32_t)(r * LDQ * 2 + c * 16),
             qkv + (size_t)((qt * 64 + r) * BB + b) * D3 + qoff + c * 8);
    }

    auto loadKV = [&](int s, int kt) {
        for (int i = tid; i < 512; i += 128) {
            int r = i >> 3, c = i & 7;
            size_t row = (size_t)((kt * 64 + r) * BB + b) * D3;
            cp16(sK + (uint32_t)(s * TILEB + r * LDQ * 2 + c * 16), qkv + row + koff + c * 8);
            cp16(sV + (uint32_t)(s * TILEB + r * LDQ * 2 + c * 16), qkv + row + voff + c * 8);
        }
        CP_COMMIT();
    };

    loadKV(0, 0);
    if (qt > 0) loadKV(1, 1); else CP_COMMIT();

    const uint32_t aQ = sQ + (uint32_t)((wr + (lane & 15)) * LDQ) * 2u
                           + (uint32_t)((lane >> 4) << 4);
    const uint32_t aP = sP + (uint32_t)((wr + (lane & 15)) * LDQ) * 2u
                           + (uint32_t)((lane >> 4) << 4);
    const uint32_t bKo = (uint32_t)(((lane & 7) + ((lane & 16) >> 1)) * LDQ) * 2u
                           + (uint32_t)(((lane >> 3) & 1) << 4);
    const uint32_t vTo = (uint32_t)((lane & 15) * LDQ) * 2u
                           + (uint32_t)(((lane & 16) >> 1) << 1);

    float m[2] = {-1e30f, -1e30f}, l[2] = {0.f, 0.f};
    float o[8][4];
#pragma unroll
    for (int ni = 0; ni < 8; ++ni)
#pragma unroll
        for (int c = 0; c < 4; ++c) o[ni][c] = 0.0f;

    for (int kt = 0; kt <= qt; ++kt) {
        const int st = kt & 1;
        CP_WAIT(1);
        __syncthreads();

        const uint32_t Kst = sK + (uint32_t)st * TILEB;
        const uint32_t Vst = sV + (uint32_t)st * TILEB;

        float s[8][4];
#pragma unroll
        for (int ni = 0; ni < 8; ++ni)
#pragma unroll
            for (int c = 0; c < 4; ++c) s[ni][c] = 0.0f;

#pragma unroll
        for (int kc = 0; kc < 4; ++kc) {
            uint32_t qf[4];
            LDSM4(qf[0], qf[1], qf[2], qf[3], aQ + (uint32_t)(kc * 32));
#pragma unroll
            for (int p = 0; p < 4; ++p) {
                uint32_t b0, b1, b2, b3;
                LDSM4(b0, b1, b2, b3,
                      Kst + bKo + (uint32_t)(p * 16 * LDQ * 2 + kc * 32));
                MMA_F16(s[2*p][0],   s[2*p][1],   s[2*p][2],   s[2*p][3],
                        qf[0], qf[1], qf[2], qf[3], b0, b1);
                MMA_F16(s[2*p+1][0], s[2*p+1][1], s[2*p+1][2], s[2*p+1][3],
                        qf[0], qf[1], qf[2], qf[3], b2, b3);
            }
        }

#pragma unroll
        for (int ni = 0; ni < 8; ++ni)
#pragma unroll
            for (int c = 0; c < 4; ++c) s[ni][c] *= 0.125f;

        if (kt == qt) {
#pragma unroll
            for (int ni = 0; ni < 8; ++ni) {
#pragma unroll
                for (int c = 0; c < 4; ++c) {
                    int kl = ni * 8 + 2 * tig + (c & 1);
                    int ql = wr + gid + ((c >> 1) << 3);
                    if (kl > ql) s[ni][c] = -1e30f;
                }
            }
        }

#pragma unroll
        for (int hf = 0; hf < 2; ++hf) {
            float mx = -1e30f;
#pragma unroll
            for (int ni = 0; ni < 8; ++ni)
                mx = fmaxf(mx, fmaxf(s[ni][2 * hf], s[ni][2 * hf + 1]));
            mx = fmaxf(mx, __shfl_xor_sync(0xffffffffu, mx, 1));
            mx = fmaxf(mx, __shfl_xor_sync(0xffffffffu, mx, 2));
            float mnew  = fmaxf(m[hf], mx);
            float alpha = __expf(m[hf] - mnew);
            float rs = 0.0f;
            int prow = wr + gid + hf * 8;
#pragma unroll
            for (int ni = 0; ni < 8; ++ni) {
                float p0 = __expf(s[ni][2 * hf]     - mnew);
                float p1 = __expf(s[ni][2 * hf + 1] - mnew);
                rs += p0 + p1;
                *(__half2*)(Pgen + prow * LDQ + ni * 8 + 2 * tig) =
                    __floats2half2_rn(p0, p1);
            }
            rs += __shfl_xor_sync(0xffffffffu, rs, 1);
            rs += __shfl_xor_sync(0xffffffffu, rs, 2);
            l[hf] = l[hf] * alpha + rs;
            m[hf] = mnew;
#pragma unroll
            for (int ni = 0; ni < 8; ++ni) {
                o[ni][2 * hf]     *= alpha;
                o[ni][2 * hf + 1] *= alpha;
            }
        }
        __syncwarp();

#pragma unroll
        for (int kc = 0; kc < 4; ++kc) {
            uint32_t pf[4];
            LDSM4(pf[0], pf[1], pf[2], pf[3], aP + (uint32_t)(kc * 32));
#pragma unroll
            for (int p = 0; p < 4; ++p) {
                uint32_t b0, b1, b2, b3;
                LDSM4T(b0, b1, b2, b3,
                       Vst + vTo + (uint32_t)(kc * 16 * LDQ * 2 + p * 32));
                MMA_F16(o[2*p][0],   o[2*p][1],   o[2*p][2],   o[2*p][3],
                        pf[0], pf[1], pf[2], pf[3], b0, b1);
                MMA_F16(o[2*p+1][0], o[2*p+1][1], o[2*p+1][2], o[2*p+1][3],
                        pf[0], pf[1], pf[2], pf[3], b2, b3);
            }
        }

        __syncthreads();
        if (kt + 2 <= qt) loadKV(st, kt + 2);
        else              CP_COMMIT();
    }

#pragma unroll
    for (int hf = 0; hf < 2; ++hf) {
        int row = qt * 64 + wr + gid + hf * 8;
        float inv = 1.0f / l[hf];
        __half* op = outp + (size_t)(row * BB + b) * DD + h * HDIM;
#pragma unroll
        for (int ni = 0; ni < 8; ++ni)
            *(__half2*)(op + ni * 8 + 2 * tig) =
                __floats2half2_rn(o[ni][2 * hf] * inv, o[ni][2 * hf + 1] * inv);
    }
}

// ---------------------------------------------------------------------------
// Residual add + LayerNorm over D=1024. One block (256 thr) per row.
// ---------------------------------------------------------------------------
template <int DUAL>
__global__ void __launch_bounds__(256)
add_ln_kernel(const float* __restrict__ y, const float* __restrict__ res,
              const float* __restrict__ g, const float* __restrict__ beta,
              float* __restrict__ out, __half* __restrict__ out16)
{
    const int row = blockIdx.x;
    const int tid = threadIdx.x;

    float4 a = ((const float4*)(y   + (size_t)row * DD))[tid];
    float4 r = ((const float4*)(res + (size_t)row * DD))[tid];
    float v0 = a.x + r.x, v1 = a.y + r.y, v2 = a.z + r.z, v3 = a.w + r.w;

    float s  = v0 + v1 + v2 + v3;
    float ss = v0 * v0 + v1 * v1 + v2 * v2 + v3 * v3;

#pragma unroll
    for (int o = 16; o > 0; o >>= 1) {
        s  += __shfl_xor_sync(0xffffffffu, s,  o);
        ss += __shfl_xor_sync(0xffffffffu, ss, o);
    }
    __shared__ float2 red[8];
    if ((tid & 31) == 0) red[tid >> 5] = make_float2(s, ss);
    __syncthreads();
    float sx = 0.f, sxx = 0.f;
#pragma unroll
    for (int i = 0; i < 8; ++i) { sx += red[i].x; sxx += red[i].y; }

    const float invD = 1.0f / (float)DD;
    float mean = sx * invD;
    float var  = fmaxf(sxx * invD - mean * mean, 0.0f);
    float rstd = rsqrtf(var + 1e-5f);

    float4 gg = ((const float4*)g)[tid];
    float4 bb = ((const float4*)beta)[tid];
    float4 o;
    o.x = (v0 - mean) * rstd * gg.x + bb.x;
    o.y = (v1 - mean) * rstd * gg.y + bb.y;
    o.z = (v2 - mean) * rstd * gg.z + bb.z;
    o.w = (v3 - mean) * rstd * gg.w + bb.w;
    ((float4*)(out + (size_t)row * DD))[tid] = o;
    if (DUAL) {
        __half* d = out16 + (size_t)row * DD + tid * 4;
        *(__half2*)(d)     = __floats2half2_rn(o.x, o.y);
        *(__half2*)(d + 2) = __floats2half2_rn(o.z, o.w);
    }
}

// ---------------------------------------------------------------------------
// Launch
// ---------------------------------------------------------------------------
extern "C" void kernel_launch(void* const* d_in, const int* in_sizes, int n_in,
                              void* d_out, int out_size)
{
    const float* x         = (const float*)d_in[0];
    const float* in_proj_w = (const float*)d_in[2];
    const float* in_proj_b = (const float*)d_in[3];
    const float* out_w     = (const float*)d_in[4];
    const float* out_b     = (const float*)d_in[5];
    const float* fc1_w     = (const float*)d_in[6];
    const float* fc1_b     = (const float*)d_in[7];
    const float* fc2_w     = (const float*)d_in[8];
    const float* fc2_b     = (const float*)d_in[9];
    const float* ln1_g     = (const float*)d_in[10];
    const float* ln1_b     = (const float*)d_in[11];
    const float* ln2_g     = (const float*)d_in[12];
    const float* ln2_b     = (const float*)d_in[13];
    float* out = (float*)d_out;

    float *h, *tmp;
    __half *qkv16, *x16, *attn16, *h16, *ff16, *wqkv16, *wout16, *wfc116, *wfc216;
    cudaGetSymbolAddress((void**)&h,      g_h);
    cudaGetSymbolAddress((void**)&tmp,    g_tmp);
    cudaGetSymbolAddress((void**)&qkv16,  g_qkv16);
    cudaGetSymbolAddress((void**)&x16,    g_x16);
    cudaGetSymbolAddress((void**)&attn16, g_attn16);
    cudaGetSymbolAddress((void**)&h16,    g_h16);
    cudaGetSymbolAddress((void**)&ff16,   g_ff16);
    cudaGetSymbolAddress((void**)&wqkv16, g_wqkv16);
    cudaGetSymbolAddress((void**)&wout16, g_wout16);
    cudaGetSymbolAddress((void**)&wfc116, g_wfc116);
    cudaGetSymbolAddress((void**)&wfc216, g_wfc216);

    cudaFuncSetAttribute(gemm_h<0,1>,
                         cudaFuncAttributeMaxDynamicSharedMemorySize, GEMMH_SMEM);
    cudaFuncSetAttribute(gemm_h<0,0>,
                         cudaFuncAttributeMaxDynamicSharedMemorySize, GEMMH_SMEM);
    cudaFuncSetAttribute(gemm_h<1,1>,
                         cudaFuncAttributeMaxDynamicSharedMemorySize, GEMMH_SMEM);
    cudaFuncSetAttribute(attn_h,
                         cudaFuncAttributeMaxDynamicSharedMemorySize, ATTN_SMEM);

    // 0) all fp32->fp16 conversions in ONE launch
    f2h5_kernel<<<(CVT_TOTAL / 4 + 255) / 256, 256>>>(
        x, x16, in_proj_w, wqkv16, out_w, wout16,
        fc1_w, wfc116, fc2_w, wfc216);

    // 1) fused QKV projection -> fp16 qkv  (768 CTAs)
    gemm_h<0,1><<<dim3(D3 / 128, MM / 128), 256, GEMMH_SMEM>>>(
        x16, wqkv16, in_proj_b, nullptr, qkv16, MM, D3, DD);

    // 2) causal flash attention (fp16, longest-first) -> fp16 attn
    attn_h<<<dim3(TT / 64, HH, BB), 128, ATTN_SMEM>>>(qkv16, attn16);

    // 3) output projection -> fp32 tmp
    gemm_h<0,0><<<dim3(DD / 128, MM / 128), 256, GEMMH_SMEM>>>(
        attn16, wout16, out_b, tmp, nullptr, MM, DD, DD);

    // 4) h = LN1(x + attn_proj), dual fp32+fp16
    add_ln_kernel<1><<<MM, 256>>>(tmp, x, ln1_g, ln1_b, h, h16);

    // 5) fc1 + gelu -> fp16 ff  (1024 CTAs)
    gemm_h<1,1><<<dim3(FFD / 128, MM / 128), 256, GEMMH_SMEM>>>(
        h16, wfc116, fc1_b, nullptr, ff16, MM, FFD, DD);

    // 6) fc2 -> fp32 tmp
    gemm_h<0,0><<<dim3(DD / 128, MM / 128), 256, GEMMH_SMEM>>>(
        ff16, wfc216, fc2_b, tmp, nullptr, MM, DD, FFD);

    // 7) out = LN2(h + ff2)
    add_ln_kernel<0><<<MM, 256>>>(tmp, h, ln2_g, ln2_b, out, nullptr);
}

// round 14
// speedup vs baseline: 1.1115x; 1.1115x over previous
#include <cuda_runtime.h>
#include <cuda_fp16.h>
#include <cstdint>
#include <cstddef>

// ---------------------------------------------------------------------------
// Problem constants
// ---------------------------------------------------------------------------
#define TT   2048
#define BB   2
#define DD   1024
#define HH   16
#define HDIM 64
#define FFD  4096
#define MM   (TT * BB)          // 4096 rows
#define D3   (3 * DD)           // 3072

// ---------------------------------------------------------------------------
// Scratch (device globals; no runtime allocation allowed)
// ---------------------------------------------------------------------------
__device__ float  g_h   [MM * DD];     // post-LN1 fp32 (residual for LN2)
__device__ float  g_tmp [MM * DD];     // fp32 gemm staging
__device__ __half g_qkv16 [MM * D3];   // fp16 qkv (attention input)
__device__ __half g_x16   [MM * DD];
__device__ __half g_attn16[MM * DD];
__device__ __half g_h16   [MM * DD];
__device__ __half g_ff16  [MM * FFD];
__device__ __half g_wqkv16[D3 * DD];
__device__ __half g_wout16[DD * DD];
__device__ __half g_wfc116[FFD * DD];
__device__ __half g_wfc216[DD * FFD];

__device__ __forceinline__ float gelu_f(float v) {
    const float c = 0.7978845608028654f;   // sqrt(2/pi)
    float t = tanhf(c * (v + 0.044715f * v * v * v));
    return 0.5f * v * (1.0f + t);
}

#define MMA_F16(d0,d1,d2,d3,a0,a1,a2,a3,b0,b1)                                \
    asm volatile(                                                             \
        "mma.sync.aligned.m16n8k16.row.col.f32.f16.f16.f32 "                  \
        "{%0,%1,%2,%3}, {%4,%5,%6,%7}, {%8,%9}, {%0,%1,%2,%3};\n"             \
        : "+f"(d0), "+f"(d1), "+f"(d2), "+f"(d3)                              \
        : "r"(a0), "r"(a1), "r"(a2), "r"(a3), "r"(b0), "r"(b1))

#define LDSM4(r0,r1,r2,r3,addr)                                               \
    asm volatile("ldmatrix.sync.aligned.m8n8.x4.shared.b16 {%0,%1,%2,%3}, [%4];" \
        : "=r"(r0), "=r"(r1), "=r"(r2), "=r"(r3) : "r"(addr))

#define LDSM4T(r0,r1,r2,r3,addr)                                              \
    asm volatile("ldmatrix.sync.aligned.m8n8.x4.trans.shared.b16 {%0,%1,%2,%3}, [%4];" \
        : "=r"(r0), "=r"(r1), "=r"(r2), "=r"(r3) : "r"(addr))

__device__ __forceinline__ void cp16(uint32_t dst, const void* src) {
    asm volatile("cp.async.cg.shared.global [%0], [%1], 16;\n"
                 :: "r"(dst), "l"(src));
}
#define CP_COMMIT() asm volatile("cp.async.commit_group;\n")
#define CP_WAIT(n)  asm volatile("cp.async.wait_group %0;\n" :: "n"(n))

// ---------------------------------------------------------------------------
// Fused fp32 -> fp16 convert, 5 segments, one launch. Block = 4096 elements
// (all segment sizes are multiples of 4096 -> no straddle). Each thread does
// 4 independent float4 loads (MLP=4) to hide DRAM latency.
// ---------------------------------------------------------------------------
#define CVT_N0 (MM * DD)     // x
#define CVT_N1 (D3 * DD)     // wqkv
#define CVT_N2 (DD * DD)     // wout
#define CVT_N3 (FFD * DD)    // wfc1
#define CVT_N4 (DD * FFD)    // wfc2
#define CVT_TOTAL (CVT_N0 + CVT_N1 + CVT_N2 + CVT_N3 + CVT_N4)

__global__ void __launch_bounds__(256)
f2h5_kernel(const float* __restrict__ s0, __half* __restrict__ d0,
            const float* __restrict__ s1, __half* __restrict__ d1,
            const float* __restrict__ s2, __half* __restrict__ d2,
            const float* __restrict__ s3, __half* __restrict__ d3,
            const float* __restrict__ s4, __half* __restrict__ d4)
{
    long long base = (long long)blockIdx.x * 4096;
    const float* src;
    __half* dst;
    long long off;
    if (base < CVT_N0)                        { src = s0; dst = d0; off = base; }
    else if (base < CVT_N0 + CVT_N1)          { src = s1; dst = d1; off = base - CVT_N0; }
    else if (base < CVT_N0 + CVT_N1 + CVT_N2) { src = s2; dst = d2; off = base - CVT_N0 - CVT_N1; }
    else if (base < (long long)CVT_N0 + CVT_N1 + CVT_N2 + CVT_N3)
                                              { src = s3; dst = d3; off = base - CVT_N0 - CVT_N1 - CVT_N2; }
    else                                      { src = s4; dst = d4; off = base - CVT_N0 - CVT_N1 - CVT_N2 - (long long)CVT_N3; }

    const int t4 = threadIdx.x * 4;
    float4 v[4];
#pragma unroll
    for (int j = 0; j < 4; ++j)
        v[j] = *(const float4*)(src + off + t4 + j * 1024);
#pragma unroll
    for (int j = 0; j < 4; ++j) {
        __half* d = dst + off + t4 + j * 1024;
        *(__half2*)(d)     = __floats2half2_rn(v[j].x, v[j].y);
        *(__half2*)(d + 2) = __floats2half2_rn(v[j].z, v[j].w);
    }
}

// ---------------------------------------------------------------------------
// fp16 tensor-core GEMM 128x128 (R12 config, best known): BK=32, 4-stage
// cp.async, batched ldmatrix. 256 thr, 2 CTAs/SM.
// ---------------------------------------------------------------------------
#define BKH      32
#define LDAH     40
#define HSTG     (128 * LDAH)
#define HSTAGES  4
#define GEMMH_SMEM (HSTAGES * 2 * HSTG * 2) // 81920 bytes
#define STGB     (2u * HSTG * 2u)

template <int ACT, int OUTH>
__global__ void __launch_bounds__(256, 2)
gemm_h(const __half* __restrict__ A, const __half* __restrict__ W,
       const float* __restrict__ bias, float* __restrict__ Cf,
       __half* __restrict__ Ch, int M, int N, int K)
{
    extern __shared__ uint32_t sm[];
    const uint32_t smem0 = (uint32_t)__cvta_generic_to_shared(sm);

    const int tid  = threadIdx.x;
    const int m0   = blockIdx.y * 128;
    const int n0   = blockIdx.x * 128;
    const int warp = tid >> 5, lane = tid & 31;
    const int gid  = lane >> 2, tig = lane & 3;
    const int wm   = (warp & 1) * 64;
    const int wn   = (warp >> 1) * 32;

    float acc[4][4][4];
#pragma unroll
    for (int i = 0; i < 4; ++i)
#pragma unroll
        for (int j = 0; j < 4; ++j)
#pragma unroll
            for (int c = 0; c < 4; ++c) acc[i][j][c] = 0.0f;

    const int lr = tid >> 1;
    const int hc = (tid & 1) << 4;
    const __half* Ag = A + (size_t)(m0 + lr) * K + hc;
    const __half* Wg = W + (size_t)(n0 + lr) * K + hc;
    const uint32_t sA = smem0 + (uint32_t)(lr * LDAH + hc) * 2u;
    const uint32_t sW = sA + (uint32_t)HSTG * 2u;

    auto LOAD = [&](int s, int k0) {
        uint32_t off = (uint32_t)s * STGB;
        cp16(sA + off,      Ag + k0);
        cp16(sA + off + 16, Ag + k0 + 8);
        cp16(sW + off,      Wg + k0);
        cp16(sW + off + 16, Wg + k0 + 8);
        CP_COMMIT();
    };

    const uint32_t aBase = smem0 + (uint32_t)((wm + (lane & 15)) * LDAH) * 2u
                                 + (uint32_t)((lane >> 4) << 4);
    const uint32_t bBase = smem0 + (uint32_t)HSTG * 2u
                                 + (uint32_t)((wn + (lane & 7) + ((lane & 16) >> 1)) * LDAH) * 2u
                                 + (uint32_t)(((lane >> 3) & 1) << 4);

    auto COMPUTE = [&](int s) {
        const uint32_t off = (uint32_t)s * STGB;
        uint32_t af[2][4][4], bf[2][4][2];
#pragma unroll
        for (int half = 0; half < 2; ++half) {
            const uint32_t ko = (uint32_t)(half << 5);
#pragma unroll
            for (int mi = 0; mi < 4; ++mi)
                LDSM4(af[half][mi][0], af[half][mi][1],
                      af[half][mi][2], af[half][mi][3],
                      aBase + off + (uint32_t)(mi * 16 * LDAH * 2) + ko);
#pragma unroll
            for (int p = 0; p < 2; ++p)
                LDSM4(bf[half][2*p][0],   bf[half][2*p][1],
                      bf[half][2*p+1][0], bf[half][2*p+1][1],
                      bBase + off + (uint32_t)(p * 16 * LDAH * 2) + ko);
        }
#pragma unroll
        for (int half = 0; half < 2; ++half)
#pragma unroll
            for (int mi = 0; mi < 4; ++mi)
#pragma unroll
                for (int ni = 0; ni < 4; ++ni)
                    MMA_F16(acc[mi][ni][0], acc[mi][ni][1],
                            acc[mi][ni][2], acc[mi][ni][3],
                            af[half][mi][0], af[half][mi][1],
                            af[half][mi][2], af[half][mi][3],
                            bf[half][ni][0], bf[half][ni][1]);
    };

    const int NCH = K / BKH;
    LOAD(0, 0);
    LOAD(1, BKH);
    LOAD(2, 2 * BKH);
    for (int i = 0; i < NCH; ++i) {
        CP_WAIT(2);
        __syncthreads();
        if (i + 3 < NCH) LOAD((i + 3) % HSTAGES, (i + 3) * BKH);
        else             CP_COMMIT();
        COMPUTE(i % HSTAGES);
    }
    __syncthreads();

#pragma unroll
    for (int mi = 0; mi < 4; ++mi) {
#pragma unroll
        for (int ni = 0; ni < 4; ++ni) {
            int col = n0 + wn + ni * 8 + 2 * tig;
            float b0 = bias[col], b1 = bias[col + 1];
            int row = m0 + wm + mi * 16 + gid;
            float v0 = acc[mi][ni][0] + b0;
            float v1 = acc[mi][ni][1] + b1;
            float v2 = acc[mi][ni][2] + b0;
            float v3 = acc[mi][ni][3] + b1;
            if (ACT == 1) {
                v0 = gelu_f(v0); v1 = gelu_f(v1);
                v2 = gelu_f(v2); v3 = gelu_f(v3);
            }
            if (OUTH) {
                *(__half2*)(Ch + (size_t)row * N + col)       = __floats2half2_rn(v0, v1);
                *(__half2*)(Ch + (size_t)(row + 8) * N + col) = __floats2half2_rn(v2, v3);
            } else {
                *(float2*)(Cf + (size_t)row * N + col)       = make_float2(v0, v1);
                *(float2*)(Cf + (size_t)(row + 8) * N + col) = make_float2(v2, v3);
            }
        }
    }
}

// ---------------------------------------------------------------------------
// fp16 GEMM 64x128 (R11, passing): for the wave-starved attn-out GEMM only.
// 8 warps each 32x32. Stage = (64+128)*LDAH halfs.
// ---------------------------------------------------------------------------
#define H64STG   ((64 + 128) * LDAH)
#define GEMM64_SMEM (HSTAGES * H64STG * 2)   // 61440 bytes
#define STGB64   ((uint32_t)H64STG * 2u)

template <int ACT>
__global__ void __launch_bounds__(256, 2)
gemm_h64(const __half* __restrict__ A, const __half* __restrict__ W,
         const float* __restrict__ bias, float* __restrict__ Cf,
         int M, int N, int K)
{
    extern __shared__ uint32_t sm[];
    const uint32_t smem0 = (uint32_t)__cvta_generic_to_shared(sm);

    const int tid  = threadIdx.x;
    const int m0   = blockIdx.y * 64;
    const int n0   = blockIdx.x * 128;
    const int warp = tid >> 5, lane = tid & 31;
    const int gid  = lane >> 2, tig = lane & 3;
    const int wm   = (warp & 1) * 32;
    const int wn   = (warp >> 1) * 32;

    float acc[2][4][4];
#pragma unroll
    for (int i = 0; i < 2; ++i)
#pragma unroll
        for (int j = 0; j < 4; ++j)
#pragma unroll
            for (int c = 0; c < 4; ++c) acc[i][j][c] = 0.0f;

    const int ar = tid >> 2, ac = (tid & 3) << 3;
    const __half* Ag = A + (size_t)(m0 + ar) * K + ac;
    const __half* Wg0 = W + (size_t)(n0 + ar) * K + ac;
    const __half* Wg1 = W + (size_t)(n0 + ar + 64) * K + ac;
    const uint32_t sA = smem0 + (uint32_t)(ar * LDAH + ac) * 2u;
    const uint32_t sW0 = smem0 + (uint32_t)(64 * LDAH) * 2u
                               + (uint32_t)(ar * LDAH + ac) * 2u;
    const uint32_t sW1 = sW0 + (uint32_t)(64 * LDAH) * 2u;

    auto LOAD = [&](int s, int k0) {
        uint32_t off = (uint32_t)s * STGB64;
        cp16(sA + off,  Ag  + k0);
        cp16(sW0 + off, Wg0 + k0);
        cp16(sW1 + off, Wg1 + k0);
        CP_COMMIT();
    };

    const uint32_t aBase = smem0 + (uint32_t)((wm + (lane & 15)) * LDAH) * 2u
                                 + (uint32_t)((lane >> 4) << 4);
    const uint32_t bBase = smem0 + (uint32_t)(64 * LDAH) * 2u
                                 + (uint32_t)((wn + (lane & 7) + ((lane & 16) >> 1)) * LDAH) * 2u
                                 + (uint32_t)(((lane >> 3) & 1) << 4);

    auto COMPUTE = [&](int s) {
        const uint32_t off = (uint32_t)s * STGB64;
#pragma unroll
        for (int kk = 0; kk < BKH; kk += 16) {
            uint32_t af[2][4], bf[4][2];
#pragma unroll
            for (int mi = 0; mi < 2; ++mi)
                LDSM4(af[mi][0], af[mi][1], af[mi][2], af[mi][3],
                      aBase + off + (uint32_t)(mi * 16 * LDAH * 2 + kk * 2));
#pragma unroll
            for (int p = 0; p < 2; ++p)
                LDSM4(bf[2*p][0], bf[2*p][1], bf[2*p+1][0], bf[2*p+1][1],
                      bBase + off + (uint32_t)(p * 16 * LDAH * 2 + kk * 2));
#pragma unroll
            for (int mi = 0; mi < 2; ++mi)
#pragma unroll
                for (int ni = 0; ni < 4; ++ni)
                    MMA_F16(acc[mi][ni][0], acc[mi][ni][1],
                            acc[mi][ni][2], acc[mi][ni][3],
                            af[mi][0], af[mi][1], af[mi][2], af[mi][3],
                            bf[ni][0], bf[ni][1]);
        }
    };

    const int NCH = K / BKH;
    LOAD(0, 0);
    LOAD(1, BKH);
    LOAD(2, 2 * BKH);
    for (int i = 0; i < NCH; ++i) {
        CP_WAIT(2);
        __syncthreads();
        if (i + 3 < NCH) LOAD((i + 3) % HSTAGES, (i + 3) * BKH);
        else             CP_COMMIT();
        COMPUTE(i % HSTAGES);
    }
    __syncthreads();

#pragma unroll
    for (int mi = 0; mi < 2; ++mi) {
#pragma unroll
        for (int ni = 0; ni < 4; ++ni) {
            int col = n0 + wn + ni * 8 + 2 * tig;
            float b0 = bias[col], b1 = bias[col + 1];
            int row = m0 + wm + mi * 16 + gid;
            float v0 = acc[mi][ni][0] + b0;
            float v1 = acc[mi][ni][1] + b1;
            float v2 = acc[mi][ni][2] + b0;
            float v3 = acc[mi][ni][3] + b1;
            if (ACT == 1) {
                v0 = gelu_f(v0); v1 = gelu_f(v1);
                v2 = gelu_f(v2); v3 = gelu_f(v3);
            }
            *(float2*)(Cf + (size_t)row * N + col)       = make_float2(v0, v1);
            *(float2*)(Cf + (size_t)(row + 8) * N + col) = make_float2(v2, v3);
        }
    }
}

// ---------------------------------------------------------------------------
// Flash attention (causal), fp16 MMA (R10/R12, passing). qt reversed.
// ---------------------------------------------------------------------------
#define LDQ   72
#define TILEB (64 * LDQ * 2)                   // 9216 bytes
#define ATTN_SMEM (6 * TILEB)                  // 55296 bytes

__global__ void __launch_bounds__(128)
attn_h(const __half* __restrict__ qkv, __half* __restrict__ outp)
{
    extern __shared__ char asmem[];
    const uint32_t smem0 = (uint32_t)__cvta_generic_to_shared(asmem);
    const uint32_t sQ = smem0;
    const uint32_t sP = smem0 + TILEB;
    const uint32_t sK = smem0 + 2 * TILEB;     // 2 stages
    const uint32_t sV = smem0 + 4 * TILEB;     // 2 stages
    __half* Pgen = (__half*)(asmem + TILEB);

    const int qt = (int)gridDim.x - 1 - (int)blockIdx.x;   // longest first
    const int h = blockIdx.y, b = blockIdx.z;
    const int tid = threadIdx.x;
    const int warp = tid >> 5, lane = tid & 31;
    const int gid = lane >> 2, tig = lane & 3;
    const int wr = warp * 16;

    const int qoff = h * HDIM;
    const int koff = DD + h * HDIM;
    const int voff = 2 * DD + h * HDIM;

    for (int i = tid; i < 512; i += 128) {
        int r = i >> 3, c = i & 7;
        cp16(sQ + (uint32_t)(r * LDQ * 2 + c * 16),
             qkv + (size_t)((qt * 64 + r) * BB + b) * D3 + qoff + c * 8);
    }

    auto loadKV = [&](int s, int kt) {
        for (int i = tid; i < 512; i += 128) {
            int r = i >> 3, c = i & 7;
            size_t row = (size_t)((kt * 64 + r) * BB + b) * D3;
            cp16(sK + (uint32_t)(s * TILEB + r * LDQ * 2 + c * 16), qkv + row + koff + c * 8);
            cp16(sV + (uint32_t)(s * TILEB + r * LDQ * 2 + c * 16), qkv + row + voff + c * 8);
        }
        CP_COMMIT();
    };

    loadKV(0, 0);
    if (qt > 0) loadKV(1, 1); else CP_COMMIT();

    const uint32_t aQ = sQ + (uint32_t)((wr + (lane & 15)) * LDQ) * 2u
                           + (uint32_t)((lane >> 4) << 4);
    const uint32_t aP = sP + (uint32_t)((wr + (lane & 15)) * LDQ) * 2u
                           + (uint32_t)((lane >> 4) << 4);
    const uint32_t bKo = (uint32_t)(((lane & 7) + ((lane & 16) >> 1)) * LDQ) * 2u
                           + (uint32_t)(((lane >> 3) & 1) << 4);
    const uint32_t vTo = (uint32_t)((lane & 15) * LDQ) * 2u
                           + (uint32_t)(((lane & 16) >> 1) << 1);

    float m[2] = {-1e30f, -1e30f}, l[2] = {0.f, 0.f};
    float o[8][4];
#pragma unroll
    for (int ni = 0; ni < 8; ++ni)
#pragma unroll
        for (int c = 0; c < 4; ++c) o[ni][c] = 0.0f;

    for (int kt = 0; kt <= qt; ++kt) {
        const int st = kt & 1;
        CP_WAIT(1);
        __syncthreads();

        const uint32_t Kst = sK + (uint32_t)st * TILEB;
        const uint32_t Vst = sV + (uint32_t)st * TILEB;

        float s[8][4];
#pragma unroll
        for (int ni = 0; ni < 8; ++ni)
#pragma unroll
            for (int c = 0; c < 4; ++c) s[ni][c] = 0.0f;

#pragma unroll
        for (int kc = 0; kc < 4; ++kc) {
            uint32_t qf[4];
            LDSM4(qf[0], qf[1], qf[2], qf[3], aQ + (uint32_t)(kc * 32));
#pragma unroll
            for (int p = 0; p < 4; ++p) {
                uint32_t b0, b1, b2, b3;
                LDSM4(b0, b1, b2, b3,
                      Kst + bKo + (uint32_t)(p * 16 * LDQ * 2 + kc * 32));
                MMA_F16(s[2*p][0],   s[2*p][1],   s[2*p][2],   s[2*p][3],
                        qf[0], qf[1], qf[2], qf[3], b0, b1);
                MMA_F16(s[2*p+1][0], s[2*p+1][1], s[2*p+1][2], s[2*p+1][3],
                        qf[0], qf[1], qf[2], qf[3], b2, b3);
            }
        }

#pragma unroll
        for (int ni = 0; ni < 8; ++ni)
#pragma unroll
            for (int c = 0; c < 4; ++c) s[ni][c] *= 0.125f;

        if (kt == qt) {
#pragma unroll
            for (int ni = 0; ni < 8; ++ni) {
#pragma unroll
                for (int c = 0; c < 4; ++c) {
                    int kl = ni * 8 + 2 * tig + (c & 1);
                    int ql = wr + gid + ((c >> 1) << 3);
                    if (kl > ql) s[ni][c] = -1e30f;
                }
            }
        }

#pragma unroll
        for (int hf = 0; hf < 2; ++hf) {
            float mx = -1e30f;
#pragma unroll
            for (int ni = 0; ni < 8; ++ni)
                mx = fmaxf(mx, fmaxf(s[ni][2 * hf], s[ni][2 * hf + 1]));
            mx = fmaxf(mx, __shfl_xor_sync(0xffffffffu, mx, 1));
            mx = fmaxf(mx, __shfl_xor_sync(0xffffffffu, mx, 2));
            float mnew  = fmaxf(m[hf], mx);
            float alpha = __expf(m[hf] - mnew);
            float rs = 0.0f;
            int prow = wr + gid + hf * 8;
#pragma unroll
            for (int ni = 0; ni < 8; ++ni) {
                float p0 = __expf(s[ni][2 * hf]     - mnew);
                float p1 = __expf(s[ni][2 * hf + 1] - mnew);
                rs += p0 + p1;
                *(__half2*)(Pgen + prow * LDQ + ni * 8 + 2 * tig) =
                    __floats2half2_rn(p0, p1);
            }
            rs += __shfl_xor_sync(0xffffffffu, rs, 1);
            rs += __shfl_xor_sync(0xffffffffu, rs, 2);
            l[hf] = l[hf] * alpha + rs;
            m[hf] = mnew;
#pragma unroll
            for (int ni = 0; ni < 8; ++ni) {
                o[ni][2 * hf]     *= alpha;
                o[ni][2 * hf + 1] *= alpha;
            }
        }
        __syncwarp();

#pragma unroll
        for (int kc = 0; kc < 4; ++kc) {
            uint32_t pf[4];
            LDSM4(pf[0], pf[1], pf[2], pf[3], aP + (uint32_t)(kc * 32));
#pragma unroll
            for (int p = 0; p < 4; ++p) {
                uint32_t b0, b1, b2, b3;
                LDSM4T(b0, b1, b2, b3,
                       Vst + vTo + (uint32_t)(kc * 16 * LDQ * 2 + p * 32));
                MMA_F16(o[2*p][0],   o[2*p][1],   o[2*p][2],   o[2*p][3],
                        pf[0], pf[1], pf[2], pf[3], b0, b1);
                MMA_F16(o[2*p+1][0], o[2*p+1][1], o[2*p+1][2], o[2*p+1][3],
                        pf[0], pf[1], pf[2], pf[3], b2, b3);
            }
        }

        __syncthreads();
        if (kt + 2 <= qt) loadKV(st, kt + 2);
        else              CP_COMMIT();
    }

#pragma unroll
    for (int hf = 0; hf < 2; ++hf) {
        int row = qt * 64 + wr + gid + hf * 8;
        float inv = 1.0f / l[hf];
        __half* op = outp + (size_t)(row * BB + b) * DD + h * HDIM;
#pragma unroll
        for (int ni = 0; ni < 8; ++ni)
            *(__half2*)(op + ni * 8 + 2 * tig) =
                __floats2half2_rn(o[ni][2 * hf] * inv, o[ni][2 * hf + 1] * inv);
    }
}

// ---------------------------------------------------------------------------
// Residual add + LayerNorm over D=1024. One block (256 thr) per row.
// ---------------------------------------------------------------------------
template <int DUAL>
__global__ void __launch_bounds__(256)
add_ln_kernel(const float* __restrict__ y, const float* __restrict__ res,
              const float* __restrict__ g, const float* __restrict__ beta,
              float* __restrict__ out, __half* __restrict__ out16)
{
    const int row = blockIdx.x;
    const int tid = threadIdx.x;

    float4 a = ((const float4*)(y   + (size_t)row * DD))[tid];
    float4 r = ((const float4*)(res + (size_t)row * DD))[tid];
    float v0 = a.x + r.x, v1 = a.y + r.y, v2 = a.z + r.z, v3 = a.w + r.w;

    float s  = v0 + v1 + v2 + v3;
    float ss = v0 * v0 + v1 * v1 + v2 * v2 + v3 * v3;

#pragma unroll
    for (int o = 16; o > 0; o >>= 1) {
        s  += __shfl_xor_sync(0xffffffffu, s,  o);
        ss += __shfl_xor_sync(0xffffffffu, ss, o);
    }
    __shared__ float2 red[8];
    if ((tid & 31) == 0) red[tid >> 5] = make_float2(s, ss);
    __syncthreads();
    float sx = 0.f, sxx = 0.f;
#pragma unroll
    for (int i = 0; i < 8; ++i) { sx += red[i].x; sxx += red[i].y; }

    const float invD = 1.0f / (float)DD;
    float mean = sx * invD;
    float var  = fmaxf(sxx * invD - mean * mean, 0.0f);
    float rstd = rsqrtf(var + 1e-5f);

    float4 gg = ((const float4*)g)[tid];
    float4 bb = ((const float4*)beta)[tid];
    float4 o;
    o.x = (v0 - mean) * rstd * gg.x + bb.x;
    o.y = (v1 - mean) * rstd * gg.y + bb.y;
    o.z = (v2 - mean) * rstd * gg.z + bb.z;
    o.w = (v3 - mean) * rstd * gg.w + bb.w;
    ((float4*)(out + (size_t)row * DD))[tid] = o;
    if (DUAL) {
        __half* d = out16 + (size_t)row * DD + tid * 4;
        *(__half2*)(d)     = __floats2half2_rn(o.x, o.y);
        *(__half2*)(d + 2) = __floats2half2_rn(o.z, o.w);
    }
}

// ---------------------------------------------------------------------------
// Launch
// ---------------------------------------------------------------------------
extern "C" void kernel_launch(void* const* d_in, const int* in_sizes, int n_in,
                              void* d_out, int out_size)
{
    const float* x         = (const float*)d_in[0];
    const float* in_proj_w = (const float*)d_in[2];
    const float* in_proj_b = (const float*)d_in[3];
    const float* out_w     = (const float*)d_in[4];
    const float* out_b     = (const float*)d_in[5];
    const float* fc1_w     = (const float*)d_in[6];
    const float* fc1_b     = (const float*)d_in[7];
    const float* fc2_w     = (const float*)d_in[8];
    const float* fc2_b     = (const float*)d_in[9];
    const float* ln1_g     = (const float*)d_in[10];
    const float* ln1_b     = (const float*)d_in[11];
    const float* ln2_g     = (const float*)d_in[12];
    const float* ln2_b     = (const float*)d_in[13];
    float* out = (float*)d_out;

    float *h, *tmp;
    __half *qkv16, *x16, *attn16, *h16, *ff16, *wqkv16, *wout16, *wfc116, *wfc216;
    cudaGetSymbolAddress((void**)&h,      g_h);
    cudaGetSymbolAddress((void**)&tmp,    g_tmp);
    cudaGetSymbolAddress((void**)&qkv16,  g_qkv16);
    cudaGetSymbolAddress((void**)&x16,    g_x16);
    cudaGetSymbolAddress((void**)&attn16, g_attn16);
    cudaGetSymbolAddress((void**)&h16,    g_h16);
    cudaGetSymbolAddress((void**)&ff16,   g_ff16);
    cudaGetSymbolAddress((void**)&wqkv16, g_wqkv16);
    cudaGetSymbolAddress((void**)&wout16, g_wout16);
    cudaGetSymbolAddress((void**)&wfc116, g_wfc116);
    cudaGetSymbolAddress((void**)&wfc216, g_wfc216);

    cudaFuncSetAttribute(gemm_h<0,1>,
                         cudaFuncAttributeMaxDynamicSharedMemorySize, GEMMH_SMEM);
    cudaFuncSetAttribute(gemm_h<0,0>,
                         cudaFuncAttributeMaxDynamicSharedMemorySize, GEMMH_SMEM);
    cudaFuncSetAttribute(gemm_h<1,1>,
                         cudaFuncAttributeMaxDynamicSharedMemorySize, GEMMH_SMEM);
    cudaFuncSetAttribute(gemm_h64<0>,
                         cudaFuncAttributeMaxDynamicSharedMemorySize, GEMM64_SMEM);
    cudaFuncSetAttribute(attn_h,
                         cudaFuncAttributeMaxDynamicSharedMemorySize, ATTN_SMEM);

    // 0) all fp32->fp16 conversions in ONE launch (MLP=4 per thread)
    f2h5_kernel<<<CVT_TOTAL / 4096, 256>>>(
        x, x16, in_proj_w, wqkv16, out_w, wout16,
        fc1_w, wfc116, fc2_w, wfc216);

    // 1) fused QKV projection -> fp16 qkv  (768 CTAs)
    gemm_h<0,1><<<dim3(D3 / 128, MM / 128), 256, GEMMH_SMEM>>>(
        x16, wqkv16, in_proj_b, nullptr, qkv16, MM, D3, DD);

    // 2) causal flash attention (fp16, longest-first) -> fp16 attn
    attn_h<<<dim3(TT / 64, HH, BB), 128, ATTN_SMEM>>>(qkv16, attn16);

    // 3) output projection -> fp32 tmp  (BM=64: 512 balanced CTAs, K=1024)
    gemm_h64<0><<<dim3(DD / 128, MM / 64), 256, GEMM64_SMEM>>>(
        attn16, wout16, out_b, tmp, MM, DD, DD);

    // 4) h = LN1(x + attn_proj), dual fp32+fp16
    add_ln_kernel<1><<<MM, 256>>>(tmp, x, ln1_g, ln1_b, h, h16);

    // 5) fc1 + gelu -> fp16 ff  (1024 CTAs)
    gemm_h<1,1><<<dim3(FFD / 128, MM / 128), 256, GEMMH_SMEM>>>(
        h16, wfc116, fc1_b, nullptr, ff16, MM, FFD, DD);

    // 6) fc2 -> fp32 tmp  (128x128: K=4096 needs the fat tile)
    gemm_h<0,0><<<dim3(DD / 128, MM / 128), 256, GEMMH_SMEM>>>(
        ff16, wfc216, fc2_b, tmp, nullptr, MM, DD, FFD);

    // 7) out = LN2(h + ff2)
    add_ln_kernel<0><<<MM, 256>>>(tmp, h, ln2_g, ln2_b, out, nullptr);
}

// round 15
// speedup vs baseline: 1.1235x; 1.0108x over previous
#include <cuda_runtime.h>
#include <cuda_fp16.h>
#include <cstdint>
#include <cstddef>

// ---------------------------------------------------------------------------
// Problem constants
// ---------------------------------------------------------------------------
#define TT   2048
#define BB   2
#define DD   1024
#define HH   16
#define HDIM 64
#define FFD  4096
#define MM   (TT * BB)          // 4096 rows
#define D3   (3 * DD)           // 3072

// ---------------------------------------------------------------------------
// Scratch (device globals; no runtime allocation allowed)
// ---------------------------------------------------------------------------
__device__ float  g_h   [MM * DD];
__device__ float  g_tmp [MM * DD];
__device__ __half g_qkv16 [MM * D3];
__device__ __half g_x16   [MM * DD];
__device__ __half g_attn16[MM * DD];
__device__ __half g_h16   [MM * DD];
__device__ __half g_ff16  [MM * FFD];
__device__ __half g_wqkv16[D3 * DD];
__device__ __half g_wout16[DD * DD];
__device__ __half g_wfc116[FFD * DD];
__device__ __half g_wfc216[DD * FFD];

__device__ __forceinline__ float gelu_f(float v) {
    const float c = 0.7978845608028654f;   // sqrt(2/pi)
    float t = tanhf(c * (v + 0.044715f * v * v * v));
    return 0.5f * v * (1.0f + t);
}

#define MMA_F16(d0,d1,d2,d3,a0,a1,a2,a3,b0,b1)                                \
    asm volatile(                                                             \
        "mma.sync.aligned.m16n8k16.row.col.f32.f16.f16.f32 "                  \
        "{%0,%1,%2,%3}, {%4,%5,%6,%7}, {%8,%9}, {%0,%1,%2,%3};\n"             \
        : "+f"(d0), "+f"(d1), "+f"(d2), "+f"(d3)                              \
        : "r"(a0), "r"(a1), "r"(a2), "r"(a3), "r"(b0), "r"(b1))

#define LDSM4(r0,r1,r2,r3,addr)                                               \
    asm volatile("ldmatrix.sync.aligned.m8n8.x4.shared.b16 {%0,%1,%2,%3}, [%4];" \
        : "=r"(r0), "=r"(r1), "=r"(r2), "=r"(r3) : "r"(addr))

#define LDSM4T(r0,r1,r2,r3,addr)                                              \
    asm volatile("ldmatrix.sync.aligned.m8n8.x4.trans.shared.b16 {%0,%1,%2,%3}, [%4];" \
        : "=r"(r0), "=r"(r1), "=r"(r2), "=r"(r3) : "r"(addr))

__device__ __forceinline__ void cp16(uint32_t dst, const void* src) {
    asm volatile("cp.async.cg.shared.global [%0], [%1], 16;\n"
                 :: "r"(dst), "l"(src));
}
#define CP_COMMIT() asm volatile("cp.async.commit_group;\n")
#define CP_WAIT(n)  asm volatile("cp.async.wait_group %0;\n" :: "n"(n))

// ---------------------------------------------------------------------------
// Fused fp32 -> fp16 convert (R14, passing): 5 segments, one launch, MLP=4.
// ---------------------------------------------------------------------------
#define CVT_N0 (MM * DD)
#define CVT_N1 (D3 * DD)
#define CVT_N2 (DD * DD)
#define CVT_N3 (FFD * DD)
#define CVT_N4 (DD * FFD)
#define CVT_TOTAL (CVT_N0 + CVT_N1 + CVT_N2 + CVT_N3 + CVT_N4)

__global__ void __launch_bounds__(256)
f2h5_kernel(const float* __restrict__ s0, __half* __restrict__ d0,
            const float* __restrict__ s1, __half* __restrict__ d1,
            const float* __restrict__ s2, __half* __restrict__ d2,
            const float* __restrict__ s3, __half* __restrict__ d3,
            const float* __restrict__ s4, __half* __restrict__ d4)
{
    long long base = (long long)blockIdx.x * 4096;
    const float* src;
    __half* dst;
    long long off;
    if (base < CVT_N0)                        { src = s0; dst = d0; off = base; }
    else if (base < CVT_N0 + CVT_N1)          { src = s1; dst = d1; off = base - CVT_N0; }
    else if (base < CVT_N0 + CVT_N1 + CVT_N2) { src = s2; dst = d2; off = base - CVT_N0 - CVT_N1; }
    else if (base < (long long)CVT_N0 + CVT_N1 + CVT_N2 + CVT_N3)
                                              { src = s3; dst = d3; off = base - CVT_N0 - CVT_N1 - CVT_N2; }
    else                                      { src = s4; dst = d4; off = base - CVT_N0 - CVT_N1 - CVT_N2 - (long long)CVT_N3; }

    const int t4 = threadIdx.x * 4;
    float4 v[4];
#pragma unroll
    for (int j = 0; j < 4; ++j)
        v[j] = *(const float4*)(src + off + t4 + j * 1024);
#pragma unroll
    for (int j = 0; j < 4; ++j) {
        __half* d = dst + off + t4 + j * 1024;
        *(__half2*)(d)     = __floats2half2_rn(v[j].x, v[j].y);
        *(__half2*)(d + 2) = __floats2half2_rn(v[j].z, v[j].w);
    }
}

// ---------------------------------------------------------------------------
// fp16 tensor-core GEMM 128x128 (R12 config, best known): BK=32, 4-stage
// cp.async, batched ldmatrix. 256 thr, 2 CTAs/SM. (GEMM3, fc2)
// ---------------------------------------------------------------------------
#define BKH      32
#define LDAH     40
#define HSTG     (128 * LDAH)
#define HSTAGES  4
#define GEMMH_SMEM (HSTAGES * 2 * HSTG * 2) // 81920 bytes
#define STGB     (2u * HSTG * 2u)

template <int ACT, int OUTH>
__global__ void __launch_bounds__(256, 2)
gemm_h(const __half* __restrict__ A, const __half* __restrict__ W,
       const float* __restrict__ bias, float* __restrict__ Cf,
       __half* __restrict__ Ch, int M, int N, int K)
{
    extern __shared__ uint32_t sm[];
    const uint32_t smem0 = (uint32_t)__cvta_generic_to_shared(sm);

    const int tid  = threadIdx.x;
    const int m0   = blockIdx.y * 128;
    const int n0   = blockIdx.x * 128;
    const int warp = tid >> 5, lane = tid & 31;
    const int gid  = lane >> 2, tig = lane & 3;
    const int wm   = (warp & 1) * 64;
    const int wn   = (warp >> 1) * 32;

    float acc[4][4][4];
#pragma unroll
    for (int i = 0; i < 4; ++i)
#pragma unroll
        for (int j = 0; j < 4; ++j)
#pragma unroll
            for (int c = 0; c < 4; ++c) acc[i][j][c] = 0.0f;

    const int lr = tid >> 1;
    const int hc = (tid & 1) << 4;
    const __half* Ag = A + (size_t)(m0 + lr) * K + hc;
    const __half* Wg = W + (size_t)(n0 + lr) * K + hc;
    const uint32_t sA = smem0 + (uint32_t)(lr * LDAH + hc) * 2u;
    const uint32_t sW = sA + (uint32_t)HSTG * 2u;

    auto LOAD = [&](int s, int k0) {
        uint32_t off = (uint32_t)s * STGB;
        cp16(sA + off,      Ag + k0);
        cp16(sA + off + 16, Ag + k0 + 8);
        cp16(sW + off,      Wg + k0);
        cp16(sW + off + 16, Wg + k0 + 8);
        CP_COMMIT();
    };

    const uint32_t aBase = smem0 + (uint32_t)((wm + (lane & 15)) * LDAH) * 2u
                                 + (uint32_t)((lane >> 4) << 4);
    const uint32_t bBase = smem0 + (uint32_t)HSTG * 2u
                                 + (uint32_t)((wn + (lane & 7) + ((lane & 16) >> 1)) * LDAH) * 2u
                                 + (uint32_t)(((lane >> 3) & 1) << 4);

    auto COMPUTE = [&](int s) {
        const uint32_t off = (uint32_t)s * STGB;
        uint32_t af[2][4][4], bf[2][4][2];
#pragma unroll
        for (int half = 0; half < 2; ++half) {
            const uint32_t ko = (uint32_t)(half << 5);
#pragma unroll
            for (int mi = 0; mi < 4; ++mi)
                LDSM4(af[half][mi][0], af[half][mi][1],
                      af[half][mi][2], af[half][mi][3],
                      aBase + off + (uint32_t)(mi * 16 * LDAH * 2) + ko);
#pragma unroll
            for (int p = 0; p < 2; ++p)
                LDSM4(bf[half][2*p][0],   bf[half][2*p][1],
                      bf[half][2*p+1][0], bf[half][2*p+1][1],
                      bBase + off + (uint32_t)(p * 16 * LDAH * 2) + ko);
        }
#pragma unroll
        for (int half = 0; half < 2; ++half)
#pragma unroll
            for (int mi = 0; mi < 4; ++mi)
#pragma unroll
                for (int ni = 0; ni < 4; ++ni)
                    MMA_F16(acc[mi][ni][0], acc[mi][ni][1],
                            acc[mi][ni][2], acc[mi][ni][3],
                            af[half][mi][0], af[half][mi][1],
                            af[half][mi][2], af[half][mi][3],
                            bf[half][ni][0], bf[half][ni][1]);
    };

    const int NCH = K / BKH;
    LOAD(0, 0);
    LOAD(1, BKH);
    LOAD(2, 2 * BKH);
    for (int i = 0; i < NCH; ++i) {
        CP_WAIT(2);
        __syncthreads();
        if (i + 3 < NCH) LOAD((i + 3) % HSTAGES, (i + 3) * BKH);
        else             CP_COMMIT();
        COMPUTE(i % HSTAGES);
    }
    __syncthreads();

#pragma unroll
    for (int mi = 0; mi < 4; ++mi) {
#pragma unroll
        for (int ni = 0; ni < 4; ++ni) {
            int col = n0 + wn + ni * 8 + 2 * tig;
            float b0 = bias[col], b1 = bias[col + 1];
            int row = m0 + wm + mi * 16 + gid;
            float v0 = acc[mi][ni][0] + b0;
            float v1 = acc[mi][ni][1] + b1;
            float v2 = acc[mi][ni][2] + b0;
            float v3 = acc[mi][ni][3] + b1;
            if (ACT == 1) {
                v0 = gelu_f(v0); v1 = gelu_f(v1);
                v2 = gelu_f(v2); v3 = gelu_f(v3);
            }
            if (OUTH) {
                *(__half2*)(Ch + (size_t)row * N + col)       = __floats2half2_rn(v0, v1);
                *(__half2*)(Ch + (size_t)(row + 8) * N + col) = __floats2half2_rn(v2, v3);
            } else {
                *(float2*)(Cf + (size_t)row * N + col)       = make_float2(v0, v1);
                *(float2*)(Cf + (size_t)(row + 8) * N + col) = make_float2(v2, v3);
            }
        }
    }
}

// ---------------------------------------------------------------------------
// fp16 GEMM 64x128, 3 CTAs/SM (84 regs, 61.4KB smem): for the big multi-wave
// GEMMs (QKV, fc1) where 24 resident warps can lift tensor-pipe utilization.
// ---------------------------------------------------------------------------
#define H64STG   ((64 + 128) * LDAH)
#define GEMM64_SMEM (HSTAGES * H64STG * 2)   // 61440 bytes
#define STGB64   ((uint32_t)H64STG * 2u)

template <int ACT, int OUTH>
__global__ void __launch_bounds__(256, 3)
gemm_h64(const __half* __restrict__ A, const __half* __restrict__ W,
         const float* __restrict__ bias, float* __restrict__ Cf,
         __half* __restrict__ Ch, int M, int N, int K)
{
    extern __shared__ uint32_t sm[];
    const uint32_t smem0 = (uint32_t)__cvta_generic_to_shared(sm);

    const int tid  = threadIdx.x;
    const int m0   = blockIdx.y * 64;
    const int n0   = blockIdx.x * 128;
    const int warp = tid >> 5, lane = tid & 31;
    const int gid  = lane >> 2, tig = lane & 3;
    const int wm   = (warp & 1) * 32;
    const int wn   = (warp >> 1) * 32;

    float acc[2][4][4];
#pragma unroll
    for (int i = 0; i < 2; ++i)
#pragma unroll
        for (int j = 0; j < 4; ++j)
#pragma unroll
            for (int c = 0; c < 4; ++c) acc[i][j][c] = 0.0f;

    const int ar = tid >> 2, ac = (tid & 3) << 3;
    const __half* Ag = A + (size_t)(m0 + ar) * K + ac;
    const __half* Wg0 = W + (size_t)(n0 + ar) * K + ac;
    const __half* Wg1 = W + (size_t)(n0 + ar + 64) * K + ac;
    const uint32_t sA = smem0 + (uint32_t)(ar * LDAH + ac) * 2u;
    const uint32_t sW0 = smem0 + (uint32_t)(64 * LDAH) * 2u
                               + (uint32_t)(ar * LDAH + ac) * 2u;
    const uint32_t sW1 = sW0 + (uint32_t)(64 * LDAH) * 2u;

    auto LOAD = [&](int s, int k0) {
        uint32_t off = (uint32_t)s * STGB64;
        cp16(sA + off,  Ag  + k0);
        cp16(sW0 + off, Wg0 + k0);
        cp16(sW1 + off, Wg1 + k0);
        CP_COMMIT();
    };

    const uint32_t aBase = smem0 + (uint32_t)((wm + (lane & 15)) * LDAH) * 2u
                                 + (uint32_t)((lane >> 4) << 4);
    const uint32_t bBase = smem0 + (uint32_t)(64 * LDAH) * 2u
                                 + (uint32_t)((wn + (lane & 7) + ((lane & 16) >> 1)) * LDAH) * 2u
                                 + (uint32_t)(((lane >> 3) & 1) << 4);

    auto COMPUTE = [&](int s) {
        const uint32_t off = (uint32_t)s * STGB64;
#pragma unroll
        for (int kk = 0; kk < BKH; kk += 16) {
            uint32_t af[2][4], bf[4][2];
#pragma unroll
            for (int mi = 0; mi < 2; ++mi)
                LDSM4(af[mi][0], af[mi][1], af[mi][2], af[mi][3],
                      aBase + off + (uint32_t)(mi * 16 * LDAH * 2 + kk * 2));
#pragma unroll
            for (int p = 0; p < 2; ++p)
                LDSM4(bf[2*p][0], bf[2*p][1], bf[2*p+1][0], bf[2*p+1][1],
                      bBase + off + (uint32_t)(p * 16 * LDAH * 2 + kk * 2));
#pragma unroll
            for (int mi = 0; mi < 2; ++mi)
#pragma unroll
                for (int ni = 0; ni < 4; ++ni)
                    MMA_F16(acc[mi][ni][0], acc[mi][ni][1],
                            acc[mi][ni][2], acc[mi][ni][3],
                            af[mi][0], af[mi][1], af[mi][2], af[mi][3],
                            bf[ni][0], bf[ni][1]);
        }
    };

    const int NCH = K / BKH;
    LOAD(0, 0);
    LOAD(1, BKH);
    LOAD(2, 2 * BKH);
    for (int i = 0; i < NCH; ++i) {
        CP_WAIT(2);
        __syncthreads();
        if (i + 3 < NCH) LOAD((i + 3) % HSTAGES, (i + 3) * BKH);
        else             CP_COMMIT();
        COMPUTE(i % HSTAGES);
    }
    __syncthreads();

#pragma unroll
    for (int mi = 0; mi < 2; ++mi) {
#pragma unroll
        for (int ni = 0; ni < 4; ++ni) {
            int col = n0 + wn + ni * 8 + 2 * tig;
            float b0 = bias[col], b1 = bias[col + 1];
            int row = m0 + wm + mi * 16 + gid;
            float v0 = acc[mi][ni][0] + b0;
            float v1 = acc[mi][ni][1] + b1;
            float v2 = acc[mi][ni][2] + b0;
            float v3 = acc[mi][ni][3] + b1;
            if (ACT == 1) {
                v0 = gelu_f(v0); v1 = gelu_f(v1);
                v2 = gelu_f(v2); v3 = gelu_f(v3);
            }
            if (OUTH) {
                *(__half2*)(Ch + (size_t)row * N + col)       = __floats2half2_rn(v0, v1);
                *(__half2*)(Ch + (size_t)(row + 8) * N + col) = __floats2half2_rn(v2, v3);
            } else {
                *(float2*)(Cf + (size_t)row * N + col)       = make_float2(v0, v1);
                *(float2*)(Cf + (size_t)(row + 8) * N + col) = make_float2(v2, v3);
            }
        }
    }
}

// ---------------------------------------------------------------------------
// Flash attention (causal), fp16 MMA (R10/R12, passing). qt reversed.
// ---------------------------------------------------------------------------
#define LDQ   72
#define TILEB (64 * LDQ * 2)                   // 9216 bytes
#define ATTN_SMEM (6 * TILEB)                  // 55296 bytes

__global__ void __launch_bounds__(128)
attn_h(const __half* __restrict__ qkv, __half* __restrict__ outp)
{
    extern __shared__ char asmem[];
    const uint32_t smem0 = (uint32_t)__cvta_generic_to_shared(asmem);
    const uint32_t sQ = smem0;
    const uint32_t sP = smem0 + TILEB;
    const uint32_t sK = smem0 + 2 * TILEB;     // 2 stages
    const uint32_t sV = smem0 + 4 * TILEB;     // 2 stages
    __half* Pgen = (__half*)(asmem + TILEB);

    const int qt = (int)gridDim.x - 1 - (int)blockIdx.x;   // longest first
    const int h = blockIdx.y, b = blockIdx.z;
    const int tid = threadIdx.x;
    const int warp = tid >> 5, lane = tid & 31;
    const int gid = lane >> 2, tig = lane & 3;
    const int wr = warp * 16;

    const int qoff = h * HDIM;
    const int koff = DD + h * HDIM;
    const int voff = 2 * DD + h * HDIM;

    for (int i = tid; i < 512; i += 128) {
        int r = i >> 3, c = i & 7;
        cp16(sQ + (uint32_t)(r * LDQ * 2 + c * 16),
             qkv + (size_t)((qt * 64 + r) * BB + b) * D3 + qoff + c * 8);
    }

    auto loadKV = [&](int s, int kt) {
        for (int i = tid; i < 512; i += 128) {
            int r = i >> 3, c = i & 7;
            size_t row = (size_t)((kt * 64 + r) * BB + b) * D3;
            cp16(sK + (uint32_t)(s * TILEB + r * LDQ * 2 + c * 16), qkv + row + koff + c * 8);
            cp16(sV + (uint32_t)(s * TILEB + r * LDQ * 2 + c * 16), qkv + row + voff + c * 8);
        }
        CP_COMMIT();
    };

    loadKV(0, 0);
    if (qt > 0) loadKV(1, 1); else CP_COMMIT();

    const uint32_t aQ = sQ + (uint32_t)((wr + (lane & 15)) * LDQ) * 2u
                           + (uint32_t)((lane >> 4) << 4);
    const uint32_t aP = sP + (uint32_t)((wr + (lane & 15)) * LDQ) * 2u
                           + (uint32_t)((lane >> 4) << 4);
    const uint32_t bKo = (uint32_t)(((lane & 7) + ((lane & 16) >> 1)) * LDQ) * 2u
                           + (uint32_t)(((lane >> 3) & 1) << 4);
    const uint32_t vTo = (uint32_t)((lane & 15) * LDQ) * 2u
                           + (uint32_t)(((lane & 16) >> 1) << 1);

    float m[2] = {-1e30f, -1e30f}, l[2] = {0.f, 0.f};
    float o[8][4];
#pragma unroll
    for (int ni = 0; ni < 8; ++ni)
#pragma unroll
        for (int c = 0; c < 4; ++c) o[ni][c] = 0.0f;

    for (int kt = 0; kt <= qt; ++kt) {
        const int st = kt & 1;
        CP_WAIT(1);
        __syncthreads();

        const uint32_t Kst = sK + (uint32_t)st * TILEB;
        const uint32_t Vst = sV + (uint32_t)st * TILEB;

        float s[8][4];
#pragma unroll
        for (int ni = 0; ni < 8; ++ni)
#pragma unroll
            for (int c = 0; c < 4; ++c) s[ni][c] = 0.0f;

#pragma unroll
        for (int kc = 0; kc < 4; ++kc) {
            uint32_t qf[4];
            LDSM4(qf[0], qf[1], qf[2], qf[3], aQ + (uint32_t)(kc * 32));
#pragma unroll
            for (int p = 0; p < 4; ++p) {
                uint32_t b0, b1, b2, b3;
                LDSM4(b0, b1, b2, b3,
                      Kst + bKo + (uint32_t)(p * 16 * LDQ * 2 + kc * 32));
                MMA_F16(s[2*p][0],   s[2*p][1],   s[2*p][2],   s[2*p][3],
                        qf[0], qf[1], qf[2], qf[3], b0, b1);
                MMA_F16(s[2*p+1][0], s[2*p+1][1], s[2*p+1][2], s[2*p+1][3],
                        qf[0], qf[1], qf[2], qf[3], b2, b3);
            }
        }

#pragma unroll
        for (int ni = 0; ni < 8; ++ni)
#pragma unroll
            for (int c = 0; c < 4; ++c) s[ni][c] *= 0.125f;

        if (kt == qt) {
#pragma unroll
            for (int ni = 0; ni < 8; ++ni) {
#pragma unroll
                for (int c = 0; c < 4; ++c) {
                    int kl = ni * 8 + 2 * tig + (c & 1);
                    int ql = wr + gid + ((c >> 1) << 3);
                    if (kl > ql) s[ni][c] = -1e30f;
                }
            }
        }

#pragma unroll
        for (int hf = 0; hf < 2; ++hf) {
            float mx = -1e30f;
#pragma unroll
            for (int ni = 0; ni < 8; ++ni)
                mx = fmaxf(mx, fmaxf(s[ni][2 * hf], s[ni][2 * hf + 1]));
            mx = fmaxf(mx, __shfl_xor_sync(0xffffffffu, mx, 1));
            mx = fmaxf(mx, __shfl_xor_sync(0xffffffffu, mx, 2));
            float mnew  = fmaxf(m[hf], mx);
            float alpha = __expf(m[hf] - mnew);
            float rs = 0.0f;
            int prow = wr + gid + hf * 8;
#pragma unroll
            for (int ni = 0; ni < 8; ++ni) {
                float p0 = __expf(s[ni][2 * hf]     - mnew);
                float p1 = __expf(s[ni][2 * hf + 1] - mnew);
                rs += p0 + p1;
                *(__half2*)(Pgen + prow * LDQ + ni * 8 + 2 * tig) =
                    __floats2half2_rn(p0, p1);
            }
            rs += __shfl_xor_sync(0xffffffffu, rs, 1);
            rs += __shfl_xor_sync(0xffffffffu, rs, 2);
            l[hf] = l[hf] * alpha + rs;
            m[hf] = mnew;
#pragma unroll
            for (int ni = 0; ni < 8; ++ni) {
                o[ni][2 * hf]     *= alpha;
                o[ni][2 * hf + 1] *= alpha;
            }
        }
        __syncwarp();

#pragma unroll
        for (int kc = 0; kc < 4; ++kc) {
            uint32_t pf[4];
            LDSM4(pf[0], pf[1], pf[2], pf[3], aP + (uint32_t)(kc * 32));
#pragma unroll
            for (int p = 0; p < 4; ++p) {
                uint32_t b0, b1, b2, b3;
                LDSM4T(b0, b1, b2, b3,
                       Vst + vTo + (uint32_t)(kc * 16 * LDQ * 2 + p * 32));
                MMA_F16(o[2*p][0],   o[2*p][1],   o[2*p][2],   o[2*p][3],
                        pf[0], pf[1], pf[2], pf[3], b0, b1);
                MMA_F16(o[2*p+1][0], o[2*p+1][1], o[2*p+1][2], o[2*p+1][3],
                        pf[0], pf[1], pf[2], pf[3], b2, b3);
            }
        }

        __syncthreads();
        if (kt + 2 <= qt) loadKV(st, kt + 2);
        else              CP_COMMIT();
    }

#pragma unroll
    for (int hf = 0; hf < 2; ++hf) {
        int row = qt * 64 + wr + gid + hf * 8;
        float inv = 1.0f / l[hf];
        __half* op = outp + (size_t)(row * BB + b) * DD + h * HDIM;
#pragma unroll
        for (int ni = 0; ni < 8; ++ni)
            *(__half2*)(op + ni * 8 + 2 * tig) =
                __floats2half2_rn(o[ni][2 * hf] * inv, o[ni][2 * hf + 1] * inv);
    }
}

// ---------------------------------------------------------------------------
// Residual add + LayerNorm over D=1024. One block (256 thr) per row.
// ---------------------------------------------------------------------------
template <int DUAL>
__global__ void __launch_bounds__(256)
add_ln_kernel(const float* __restrict__ y, const float* __restrict__ res,
              const float* __restrict__ g, const float* __restrict__ beta,
              float* __restrict__ out, __half* __restrict__ out16)
{
    const int row = blockIdx.x;
    const int tid = threadIdx.x;

    float4 a = ((const float4*)(y   + (size_t)row * DD))[tid];
    float4 r = ((const float4*)(res + (size_t)row * DD))[tid];
    float v0 = a.x + r.x, v1 = a.y + r.y, v2 = a.z + r.z, v3 = a.w + r.w;

    float s  = v0 + v1 + v2 + v3;
    float ss = v0 * v0 + v1 * v1 + v2 * v2 + v3 * v3;

#pragma unroll
    for (int o = 16; o > 0; o >>= 1) {
        s  += __shfl_xor_sync(0xffffffffu, s,  o);
        ss += __shfl_xor_sync(0xffffffffu, ss, o);
    }
    __shared__ float2 red[8];
    if ((tid & 31) == 0) red[tid >> 5] = make_float2(s, ss);
    __syncthreads();
    float sx = 0.f, sxx = 0.f;
#pragma unroll
    for (int i = 0; i < 8; ++i) { sx += red[i].x; sxx += red[i].y; }

    const float invD = 1.0f / (float)DD;
    float mean = sx * invD;
    float var  = fmaxf(sxx * invD - mean * mean, 0.0f);
    float rstd = rsqrtf(var + 1e-5f);

    float4 gg = ((const float4*)g)[tid];
    float4 bb = ((const float4*)beta)[tid];
    float4 o;
    o.x = (v0 - mean) * rstd * gg.x + bb.x;
    o.y = (v1 - mean) * rstd * gg.y + bb.y;
    o.z = (v2 - mean) * rstd * gg.z + bb.z;
    o.w = (v3 - mean) * rstd * gg.w + bb.w;
    ((float4*)(out + (size_t)row * DD))[tid] = o;
    if (DUAL) {
        __half* d = out16 + (size_t)row * DD + tid * 4;
        *(__half2*)(d)     = __floats2half2_rn(o.x, o.y);
        *(__half2*)(d + 2) = __floats2half2_rn(o.z, o.w);
    }
}

// ---------------------------------------------------------------------------
// Launch
// ---------------------------------------------------------------------------
extern "C" void kernel_launch(void* const* d_in, const int* in_sizes, int n_in,
                              void* d_out, int out_size)
{
    const float* x         = (const float*)d_in[0];
    const float* in_proj_w = (const float*)d_in[2];
    const float* in_proj_b = (const float*)d_in[3];
    const float* out_w     = (const float*)d_in[4];
    const float* out_b     = (const float*)d_in[5];
    const float* fc1_w     = (const float*)d_in[6];
    const float* fc1_b     = (const float*)d_in[7];
    const float* fc2_w     = (const float*)d_in[8];
    const float* fc2_b     = (const float*)d_in[9];
    const float* ln1_g     = (const float*)d_in[10];
    const float* ln1_b     = (const float*)d_in[11];
    const float* ln2_g     = (const float*)d_in[12];
    const float* ln2_b     = (const float*)d_in[13];
    float* out = (float*)d_out;

    float *h, *tmp;
    __half *qkv16, *x16, *attn16, *h16, *ff16, *wqkv16, *wout16, *wfc116, *wfc216;
    cudaGetSymbolAddress((void**)&h,      g_h);
    cudaGetSymbolAddress((void**)&tmp,    g_tmp);
    cudaGetSymbolAddress((void**)&qkv16,  g_qkv16);
    cudaGetSymbolAddress((void**)&x16,    g_x16);
    cudaGetSymbolAddress((void**)&attn16, g_attn16);
    cudaGetSymbolAddress((void**)&h16,    g_h16);
    cudaGetSymbolAddress((void**)&ff16,   g_ff16);
    cudaGetSymbolAddress((void**)&wqkv16, g_wqkv16);
    cudaGetSymbolAddress((void**)&wout16, g_wout16);
    cudaGetSymbolAddress((void**)&wfc116, g_wfc116);
    cudaGetSymbolAddress((void**)&wfc216, g_wfc216);

    cudaFuncSetAttribute(gemm_h<0,0>,
                         cudaFuncAttributeMaxDynamicSharedMemorySize, GEMMH_SMEM);
    cudaFuncSetAttribute(gemm_h64<0,1>,
                         cudaFuncAttributeMaxDynamicSharedMemorySize, GEMM64_SMEM);
    cudaFuncSetAttribute(gemm_h64<1,1>,
                         cudaFuncAttributeMaxDynamicSharedMemorySize, GEMM64_SMEM);
    cudaFuncSetAttribute(attn_h,
                         cudaFuncAttributeMaxDynamicSharedMemorySize, ATTN_SMEM);

    // 0) all fp32->fp16 conversions in ONE launch (MLP=4)
    f2h5_kernel<<<CVT_TOTAL / 4096, 256>>>(
        x, x16, in_proj_w, wqkv16, out_w, wout16,
        fc1_w, wfc116, fc2_w, wfc216);

    // 1) fused QKV projection -> fp16 qkv  (BM=64, 3 CTA/SM: 1536 CTAs)
    gemm_h64<0,1><<<dim3(D3 / 128, MM / 64), 256, GEMM64_SMEM>>>(
        x16, wqkv16, in_proj_b, nullptr, qkv16, MM, D3, DD);

    // 2) causal flash attention (fp16, longest-first) -> fp16 attn
    attn_h<<<dim3(TT / 64, HH, BB), 128, ATTN_SMEM>>>(qkv16, attn16);

    // 3) output projection -> fp32 tmp  (128x128, proven best here)
    gemm_h<0,0><<<dim3(DD / 128, MM / 128), 256, GEMMH_SMEM>>>(
        attn16, wout16, out_b, tmp, nullptr, MM, DD, DD);

    // 4) h = LN1(x + attn_proj), dual fp32+fp16
    add_ln_kernel<1><<<MM, 256>>>(tmp, x, ln1_g, ln1_b, h, h16);

    // 5) fc1 + gelu -> fp16 ff  (BM=64, 3 CTA/SM: 2048 CTAs)
    gemm_h64<1,1><<<dim3(FFD / 128, MM / 64), 256, GEMM64_SMEM>>>(
        h16, wfc116, fc1_b, nullptr, ff16, MM, FFD, DD);

    // 6) fc2 -> fp32 tmp  (128x128: K=4096 needs the fat tile)
    gemm_h<0,0><<<dim3(DD / 128, MM / 128), 256, GEMMH_SMEM>>>(
        ff16, wfc216, fc2_b, tmp, nullptr, MM, DD, FFD);

    // 7) out = LN2(h + ff2)
    add_ln_kernel<0><<<MM, 256>>>(tmp, h, ln2_g, ln2_b, out, nullptr);
}